// round 13
// baseline (speedup 1.0000x reference)
#include <cuda_runtime.h>
#include <cuda_bf16.h>
#include <mma.h>
#include <math.h>
#include <stdint.h>

using namespace nvcuda;

// Problem constants (fixed by the dataset)
#define BATCH  128
#define TSTEPS 128
#define DIM    1024
#define NCOLS  2048          // [r-block | u-block] output features
#define KP     3072          // packed K' = [hi|hi|lo] x [hi|lo|hi] split GEMM
#define NCHUNK 96            // KP / 32 (precompute)

// Precompute GEMM tiling: CTA 128x128, 4 warps of 64x64 (4x4 frags)
#define BM 128
#define BN 128
#define BK 32
#define LDW 40               // smem leading dim (bf16), 80B ≡ 80 mod 128 -> CF
#define TSZ (128 * LDW)      // one tile buffer (elems)

// Scan (persistent) kernel geometry
#define SCAN_CTAS   128      // 32 n-slices x 4 k-slices; CTA c == batch c owner
#define SCAN_THREADS 256
#define KSL         4        // k-split factor in scan
#define KSLICE      768      // KP / KSL
#define NSLICE      64
#define LDBP        776      // B-slice row stride (1552B ≡ 16 mod 128 -> CF)
#define SB_BYTES    (NSLICE * LDBP * 2)            // 99328
#define AW_ELEMS    (32 * LDW)                     // 1280 per (warp,buf)
#define SAW_BYTES   (8 * 2 * AW_ELEMS * 2)         // 40960
#define SCAN_SMEM   (SB_BYTES + SAW_BYTES)         // 140288

// ---------------- scratch (device symbols; NEVER passed from host) --------
__device__ float g_FW[(size_t)BATCH * TSTEPS * NCOLS];      // fWr||fW
__device__ float g_part[KSL * BATCH * NCOLS];               // k-split partials
__device__ __align__(16) __nv_bfloat16 g_Af[(size_t)BATCH * TSTEPS * KP];
__device__ __align__(16) __nv_bfloat16 g_Ah[BATCH * KP];
__device__ __align__(16) __nv_bfloat16 g_Bf[(size_t)NCOLS * KP];
__device__ __align__(16) __nv_bfloat16 g_Bu[(size_t)NCOLS * KP];

// software grid barrier state
__device__ int g_bar_arrive;
__device__ volatile int g_bar_gen;

// ---------------- helpers ---------------------------------------------------
__device__ __forceinline__ uint32_t smem_u32(const void* p) {
    uint32_t a;
    asm("{ .reg .u64 t; cvta.to.shared.u64 t, %1; cvt.u32.u64 %0, t; }"
        : "=r"(a) : "l"(p));
    return a;
}

__device__ __forceinline__ void cpasync16(uint32_t dst, const void* src) {
    asm volatile("cp.async.cg.shared.global [%0], [%1], 16;"
                 :: "r"(dst), "l"(src) : "memory");
}

// Grid-wide barrier: every thread fences its stores (GPU scope) before arrival.
__device__ __forceinline__ void grid_barrier() {
    __threadfence();
    __syncthreads();
    if (threadIdx.x == 0) {
        int gen = g_bar_gen;
        if (atomicAdd(&g_bar_arrive, 1) == SCAN_CTAS - 1) {
            g_bar_arrive = 0;
            __threadfence();
            g_bar_gen = gen + 1;
        } else {
            while (g_bar_gen == gen) { }
            __threadfence();
        }
    }
    __syncthreads();
}

// ---------------------------------------------------------------------------
// Precompute GEMM v2: 128x128 CTA, 4 warps, warp tile 64x64 (4x4 wmma frags).
//   C=g_FW = A'(g_Af) @ B'(g_Bf)^T, fp32 accum, cp.async double buffered.
// ---------------------------------------------------------------------------
__device__ __forceinline__ void stage_pre(uint32_t sa_base, uint32_t sb_base,
                                          int m0, int n0, int kb, int tid) {
#pragma unroll
    for (int i = 0; i < 8; ++i) {          // 256 rows (128 A + 128 B) x 4 vec
        int v = tid + 128 * i;
        int row = v >> 2, kv = v & 3;
        if (row < 128)
            cpasync16(sa_base + row * (LDW * 2) + kv * 16,
                      g_Af + (size_t)(m0 + row) * KP + kb + kv * 8);
        else
            cpasync16(sb_base + (row - 128) * (LDW * 2) + kv * 16,
                      g_Bf + (size_t)(n0 + row - 128) * KP + kb + kv * 8);
    }
    asm volatile("cp.async.commit_group;" ::: "memory");
}

__global__ __launch_bounds__(128) void gemm_pre() {
    __shared__ __align__(16) __nv_bfloat16 sa[2][TSZ];
    __shared__ __align__(16) __nv_bfloat16 sb[2][TSZ];

    const int tid = threadIdx.x, warp = tid >> 5;
    const int wm = warp >> 1, wn = warp & 1;
    const int m0 = blockIdx.y * BM, n0 = blockIdx.x * BN;
    const uint32_t sa0 = smem_u32(&sa[0][0]);
    const uint32_t sb0 = smem_u32(&sb[0][0]);

    wmma::fragment<wmma::accumulator, 16, 16, 16, float> c[4][4];
#pragma unroll
    for (int mt = 0; mt < 4; ++mt)
#pragma unroll
        for (int nt = 0; nt < 4; ++nt) wmma::fill_fragment(c[mt][nt], 0.0f);

    stage_pre(sa0, sb0, m0, n0, 0, tid);

    for (int kt = 0; kt < NCHUNK; ++kt) {
        if (kt + 1 < NCHUNK) {
            stage_pre(sa0 + ((kt + 1) & 1) * (TSZ * 2),
                      sb0 + ((kt + 1) & 1) * (TSZ * 2),
                      m0, n0, (kt + 1) * BK, tid);
            asm volatile("cp.async.wait_group 1;" ::: "memory");
        } else {
            asm volatile("cp.async.wait_group 0;" ::: "memory");
        }
        __syncthreads();

        const __nv_bfloat16* pa = &sa[kt & 1][0] + (wm * 64) * LDW;
        const __nv_bfloat16* pb = &sb[kt & 1][0] + (wn * 64) * LDW;
#pragma unroll
        for (int kk = 0; kk < 2; ++kk) {
            wmma::fragment<wmma::matrix_a, 16, 16, 16, __nv_bfloat16,
                           wmma::row_major> af[4];
            wmma::fragment<wmma::matrix_b, 16, 16, 16, __nv_bfloat16,
                           wmma::col_major> bf[4];
#pragma unroll
            for (int mt = 0; mt < 4; ++mt)
                wmma::load_matrix_sync(af[mt], pa + mt * 16 * LDW + kk * 16, LDW);
#pragma unroll
            for (int nt = 0; nt < 4; ++nt)
                wmma::load_matrix_sync(bf[nt], pb + nt * 16 * LDW + kk * 16, LDW);
#pragma unroll
            for (int mt = 0; mt < 4; ++mt)
#pragma unroll
                for (int nt = 0; nt < 4; ++nt)
                    wmma::mma_sync(c[mt][nt], af[mt], bf[nt], c[mt][nt]);
        }
        __syncthreads();
    }

    const size_t crow = (size_t)m0 + wm * 64;
    const int ccol = n0 + wn * 64;
#pragma unroll
    for (int mt = 0; mt < 4; ++mt)
#pragma unroll
        for (int nt = 0; nt < 4; ++nt)
            wmma::store_matrix_sync(g_FW + (crow + mt * 16) * NCOLS + ccol + nt * 16,
                                    c[mt][nt], NCOLS, wmma::mem_row_major);
}

// ---------------------------------------------------------------------------
// Persistent scan: warp-private A staging (no block syncs in mainloop),
// h in registers, float4 combine. CTA c: ni=c&31, ki=c>>5; batch b==c owner.
// ---------------------------------------------------------------------------
extern __shared__ __align__(16) unsigned char dynsmem[];

__global__ __launch_bounds__(SCAN_THREADS) void scan_kernel(
    const float* __restrict__ gates, const float* __restrict__ Urb,
    const float* __restrict__ Ub, const int* __restrict__ nf,
    const float* __restrict__ mem_old, float* __restrict__ out) {
    __nv_bfloat16* sB  = (__nv_bfloat16*)dynsmem;              // [64][LDBP]
    __nv_bfloat16* sAw = (__nv_bfloat16*)(dynsmem + SB_BYTES); // [8][2][32*LDW]

    const int tid = threadIdx.x;
    const int cta = blockIdx.x;
    const int ni = cta & 31, ki = cta >> 5;
    const int n0 = ni * NSLICE;
    const int k0 = ki * KSLICE;
    const int warp = tid >> 5, lane = tid & 31;
    const int wm = warp & 3, wn = warp >> 2;   // 4 m-warps x 2 n-warps

    // ---- load resident B slice [64 rows][768 k]: 96 x 16B per row ----
    for (int v = tid; v < NSLICE * 96; v += SCAN_THREADS) {
        int row = v / 96, kv = v % 96;
        *(uint4*)(sB + (size_t)row * LDBP + kv * 8) =
            *(const uint4*)(g_Bu + (size_t)(n0 + row) * KP + k0 + kv * 8);
    }

    // ---- h lives in registers: thread owns dims [4*tid, 4*tid+4) ----
    const int d = tid * 4;
    float4 h4 = *(const float4*)(mem_old + (size_t)cta * DIM + d);
    const float4 br4 = *(const float4*)(Urb + d);
    const float4 bu4 = *(const float4*)(Ub + d);
    const int tout = nf[cta] - 1;
    {
        __nv_bfloat16* row = g_Ah + (size_t)cta * KP;
        float hv[4] = {h4.x, h4.y, h4.z, h4.w};
        __nv_bfloat16 hi[4], lo[4];
#pragma unroll
        for (int j = 0; j < 4; ++j) {
            hi[j] = __float2bfloat16(hv[j]);
            lo[j] = __float2bfloat16(hv[j] - __bfloat162float(hi[j]));
        }
        uint32_t hi01 = ((uint32_t*)hi)[0], hi23 = ((uint32_t*)hi)[1];
        uint32_t lo01 = ((uint32_t*)lo)[0], lo23 = ((uint32_t*)lo)[1];
        *(uint2*)(row + d)        = make_uint2(hi01, hi23);
        *(uint2*)(row + 1024 + d) = make_uint2(hi01, hi23);
        *(uint2*)(row + 2048 + d) = make_uint2(lo01, lo23);
    }
    grid_barrier();   // g_Ah + sB ready everywhere

    const uint32_t myA = smem_u32(sAw) + (uint32_t)warp * (2 * AW_ELEMS * 2) +
                         (uint32_t)lane * (LDW * 2);
    const __nv_bfloat16* Asrc = g_Ah + (size_t)(wm * 32 + lane) * KP + k0;

    for (int t = 0; t < TSTEPS; ++t) {
        wmma::fragment<wmma::accumulator, 16, 16, 16, float> c[2][2];
#pragma unroll
        for (int mt = 0; mt < 2; ++mt)
#pragma unroll
            for (int nt = 0; nt < 2; ++nt) wmma::fill_fragment(c[mt][nt], 0.0f);

        // warp-private stage of chunk 0 (lane stages its own A row: 4 x 16B)
#pragma unroll
        for (int j = 0; j < 4; ++j)
            cpasync16(myA + j * 16, Asrc + j * 8);
        asm volatile("cp.async.commit_group;" ::: "memory");

        for (int kt = 0; kt < KSLICE / 32; ++kt) {       // 24 chunks
            if (kt + 1 < KSLICE / 32) {
                uint32_t dst = myA + ((kt + 1) & 1) * (AW_ELEMS * 2);
                const __nv_bfloat16* src = Asrc + (kt + 1) * 32;
#pragma unroll
                for (int j = 0; j < 4; ++j)
                    cpasync16(dst + j * 16, src + j * 8);
                asm volatile("cp.async.commit_group;" ::: "memory");
                asm volatile("cp.async.wait_group 1;" ::: "memory");
            } else {
                asm volatile("cp.async.wait_group 0;" ::: "memory");
            }
            __syncwarp();

            const __nv_bfloat16* pa = sAw + (warp * 2 + (kt & 1)) * AW_ELEMS;
            const __nv_bfloat16* pb = sB + (size_t)(wn * 32) * LDBP + kt * 32;
#pragma unroll
            for (int kk = 0; kk < 2; ++kk) {
                wmma::fragment<wmma::matrix_a, 16, 16, 16, __nv_bfloat16,
                               wmma::row_major> af[2];
                wmma::fragment<wmma::matrix_b, 16, 16, 16, __nv_bfloat16,
                               wmma::col_major> bf[2];
#pragma unroll
                for (int mt = 0; mt < 2; ++mt)
                    wmma::load_matrix_sync(af[mt], pa + mt * 16 * LDW + kk * 16, LDW);
#pragma unroll
                for (int nt = 0; nt < 2; ++nt)
                    wmma::load_matrix_sync(bf[nt],
                                           pb + (size_t)nt * 16 * LDBP + kk * 16,
                                           LDBP);
#pragma unroll
                for (int mt = 0; mt < 2; ++mt)
#pragma unroll
                    for (int nt = 0; nt < 2; ++nt)
                        wmma::mma_sync(c[mt][nt], af[mt], bf[nt], c[mt][nt]);
            }
        }

        // write partials: g_part[ki][m][col]
        {
            float* base = g_part + (size_t)ki * BATCH * NCOLS;
#pragma unroll
            for (int mt = 0; mt < 2; ++mt)
#pragma unroll
                for (int nt = 0; nt < 2; ++nt)
                    wmma::store_matrix_sync(
                        base + (size_t)(wm * 32 + mt * 16) * NCOLS + n0 + wn * 32 + nt * 16,
                        c[mt][nt], NCOLS, wmma::mem_row_major);
        }
        grid_barrier();   // partials published + visible everywhere

        // ===== combine: this CTA handles batch b == cta; 4 dims/thread =====
        {
            const float gt = gates[cta * TSTEPS + t];
            const float* fw = g_FW + ((size_t)cta * TSTEPS + t) * NCOLS;
            float4 pr = make_float4(0.f, 0.f, 0.f, 0.f);
            float4 pu = make_float4(0.f, 0.f, 0.f, 0.f);
#pragma unroll
            for (int s = 0; s < KSL; ++s) {
                const float* pb0 = g_part + (size_t)s * BATCH * NCOLS +
                                   (size_t)cta * NCOLS + d;
                float4 a = __ldcg((const float4*)pb0);
                float4 b = __ldcg((const float4*)(pb0 + 1024));
                pr.x += a.x; pr.y += a.y; pr.z += a.z; pr.w += a.w;
                pu.x += b.x; pu.y += b.y; pu.z += b.z; pu.w += b.w;
            }
            float4 fr = *(const float4*)(fw + d);
            float4 fu = *(const float4*)(fw + 1024 + d);

            float prv[4] = {pr.x, pr.y, pr.z, pr.w};
            float puv[4] = {pu.x, pu.y, pu.z, pu.w};
            float frv[4] = {fr.x, fr.y, fr.z, fr.w};
            float fuv[4] = {fu.x, fu.y, fu.z, fu.w};
            float brv[4] = {br4.x, br4.y, br4.z, br4.w};
            float buv[4] = {bu4.x, bu4.y, bu4.z, bu4.w};
            float hov[4] = {h4.x, h4.y, h4.z, h4.w};
            float hn[4];
            __nv_bfloat16 hi[4], lo[4];
#pragma unroll
            for (int j = 0; j < 4; ++j) {
                float r = 1.f / (1.f + expf(-(frv[j] + prv[j] + brv[j])));
                float ht = tanhf(fuv[j] + r * (puv[j] + buv[j]));
                hn[j] = gt * ht + (1.f - gt) * hov[j];
                hi[j] = __float2bfloat16(hn[j]);
                lo[j] = __float2bfloat16(hn[j] - __bfloat162float(hi[j]));
            }
            h4 = make_float4(hn[0], hn[1], hn[2], hn[3]);

            __nv_bfloat16* row = g_Ah + (size_t)cta * KP;
            uint32_t hi01 = ((uint32_t*)hi)[0], hi23 = ((uint32_t*)hi)[1];
            uint32_t lo01 = ((uint32_t*)lo)[0], lo23 = ((uint32_t*)lo)[1];
            *(uint2*)(row + d)        = make_uint2(hi01, hi23);
            *(uint2*)(row + 1024 + d) = make_uint2(hi01, hi23);
            *(uint2*)(row + 2048 + d) = make_uint2(lo01, lo23);

            if (t == tout) *(float4*)(out + (size_t)cta * DIM + d) = h4;
        }
        grid_barrier();   // repacked h published before next step's GEMM
    }
}

// ---------------------------------------------------------------------------
// packing kernels
// ---------------------------------------------------------------------------
__global__ void pack_w_kernel(const float* __restrict__ w0,
                              const float* __restrict__ w1, int which) {
    __nv_bfloat16* dst = (which == 0) ? g_Bf : g_Bu;
    size_t i = (size_t)blockIdx.x * blockDim.x + threadIdx.x;
    int n = (int)(i >> 10), k = (int)(i & 1023);
    float v = (n < 1024) ? w0[(size_t)n * 1024 + k] : w1[(size_t)(n - 1024) * 1024 + k];
    __nv_bfloat16 hi = __float2bfloat16(v);
    __nv_bfloat16 lo = __float2bfloat16(v - __bfloat162float(hi));
    __nv_bfloat16* row = dst + (size_t)n * KP;
    row[k] = hi; row[1024 + k] = lo; row[2048 + k] = hi;
}

__global__ void pack_facts_kernel(const float* __restrict__ facts) {
    size_t i = (size_t)blockIdx.x * blockDim.x + threadIdx.x;
    size_t r = i >> 10; int k = (int)(i & 1023);
    float v = facts[i];
    __nv_bfloat16 hi = __float2bfloat16(v);
    __nv_bfloat16 lo = __float2bfloat16(v - __bfloat162float(hi));
    __nv_bfloat16* row = g_Af + r * KP;
    row[k] = hi; row[1024 + k] = hi; row[2048 + k] = lo;
}

// ---------------------------------------------------------------------------
extern "C" void kernel_launch(void* const* d_in, const int* in_sizes, int n_in,
                              void* d_out, int out_size) {
    const float* facts   = (const float*)d_in[0];
    const int*   nf      = (const int*)d_in[1];
    const float* g       = (const float*)d_in[2];
    const float* mem_old = (const float*)d_in[3];
    const float* Wr      = (const float*)d_in[4];
    const float* Urw     = (const float*)d_in[5];
    const float* Urb     = (const float*)d_in[6];
    const float* W       = (const float*)d_in[7];
    const float* Uw      = (const float*)d_in[8];
    const float* Ub      = (const float*)d_in[9];
    float* out = (float*)d_out;

    cudaFuncSetAttribute(scan_kernel,
                         cudaFuncAttributeMaxDynamicSharedMemorySize,
                         SCAN_SMEM);

    pack_w_kernel<<<(2048 * 1024) / 256, 256>>>(Wr, W, /*which=*/0);
    pack_w_kernel<<<(2048 * 1024) / 256, 256>>>(Urw, Uw, /*which=*/1);
    pack_facts_kernel<<<(16384 * 1024) / 256, 256>>>(facts);

    // precompute fWr||fW : [16384, 2048] = A'(facts) @ B'(Wr;W)^T
    gemm_pre<<<dim3(NCOLS / BN, 16384 / BM, 1), 128>>>();

    // all 128 recurrence steps in one persistent launch
    scan_kernel<<<SCAN_CTAS, SCAN_THREADS, SCAN_SMEM>>>(g, Urb, Ub, nf,
                                                        mem_old, out);
}

// round 14
// speedup vs baseline: 1.4409x; 1.4409x over previous
#include <cuda_runtime.h>
#include <cuda_bf16.h>
#include <mma.h>
#include <math.h>
#include <stdint.h>

using namespace nvcuda;

// Problem constants (fixed by the dataset)
#define BATCH  128
#define TSTEPS 128
#define DIM    1024
#define NCOLS  2048          // [r-block | u-block] output features
#define KP     3072          // packed K' = [hi|hi|lo] x [hi|lo|hi] split GEMM
#define NCHUNK 96            // KP / 32 (precompute)

// Precompute GEMM tiling: CTA 128x128, 4 warps of 64x64 (4x4 frags)
#define BM 128
#define BN 128
#define BK 32
#define LDW 40               // smem leading dim (bf16), conflict-free
#define TSZ (128 * LDW)

// Scan (persistent) kernel geometry
#define SCAN_CTAS   128      // 32 n-slices x 4 k-slices; CTA c == batch c owner
#define SCAN_THREADS 256
#define KSL         8        // partial slabs: 4 CTA k-slices x 2 warp k-groups
#define KSLICE      768      // KP / 4 (per-CTA k window)
#define NSLICE      64
#define NCH_S       12       // KSLICE / 64
#define LDBP        776      // B-slice row stride (1552B mod 128 = 16 -> CF)
#define SB_BYTES    (NSLICE * LDBP * 2)            // 99328
#define LDA2        72       // A-chunk smem stride (144B mod 128 = 16 -> CF)
#define AT_ELEMS    (128 * LDA2)                   // 9216 elems / buffer
#define SA_BYTES    (2 * AT_ELEMS * 2)             // 36864
#define SCAN_SMEM   (SB_BYTES + SA_BYTES)          // 136192

// ---------------- scratch (device symbols; NEVER passed from host) --------
__device__ float g_FW[(size_t)BATCH * TSTEPS * NCOLS];      // fWr||fW
__device__ float g_part[KSL * BATCH * NCOLS];               // k-split partials
__device__ __align__(16) __nv_bfloat16 g_Af[(size_t)BATCH * TSTEPS * KP];
__device__ __align__(16) __nv_bfloat16 g_Ah[BATCH * KP];
__device__ __align__(16) __nv_bfloat16 g_Bf[(size_t)NCOLS * KP];
__device__ __align__(16) __nv_bfloat16 g_Bu[(size_t)NCOLS * KP];

// software grid barrier state
__device__ int g_bar_arrive;
__device__ volatile int g_bar_gen;

// ---------------- helpers ---------------------------------------------------
__device__ __forceinline__ uint32_t smem_u32(const void* p) {
    uint32_t a;
    asm("{ .reg .u64 t; cvta.to.shared.u64 t, %1; cvt.u32.u64 %0, t; }"
        : "=r"(a) : "l"(p));
    return a;
}

__device__ __forceinline__ void cpasync16(uint32_t dst, const void* src) {
    asm volatile("cp.async.cg.shared.global [%0], [%1], 16;"
                 :: "r"(dst), "l"(src) : "memory");
}

// Grid-wide barrier: every thread fences its stores (GPU scope) before arrival.
__device__ __forceinline__ void grid_barrier() {
    __threadfence();
    __syncthreads();
    if (threadIdx.x == 0) {
        int gen = g_bar_gen;
        if (atomicAdd(&g_bar_arrive, 1) == SCAN_CTAS - 1) {
            g_bar_arrive = 0;
            __threadfence();
            g_bar_gen = gen + 1;
        } else {
            while (g_bar_gen == gen) { }
            __threadfence();
        }
    }
    __syncthreads();
}

// ---------------------------------------------------------------------------
// Precompute GEMM (round-13, 599us measured): C=g_FW = A'(g_Af) @ B'(g_Bf)^T
// ---------------------------------------------------------------------------
__device__ __forceinline__ void stage_pre(uint32_t sa_base, uint32_t sb_base,
                                          int m0, int n0, int kb, int tid) {
#pragma unroll
    for (int i = 0; i < 8; ++i) {
        int v = tid + 128 * i;
        int row = v >> 2, kv = v & 3;
        if (row < 128)
            cpasync16(sa_base + row * (LDW * 2) + kv * 16,
                      g_Af + (size_t)(m0 + row) * KP + kb + kv * 8);
        else
            cpasync16(sb_base + (row - 128) * (LDW * 2) + kv * 16,
                      g_Bf + (size_t)(n0 + row - 128) * KP + kb + kv * 8);
    }
    asm volatile("cp.async.commit_group;" ::: "memory");
}

__global__ __launch_bounds__(128) void gemm_pre() {
    __shared__ __align__(16) __nv_bfloat16 sa[2][TSZ];
    __shared__ __align__(16) __nv_bfloat16 sb[2][TSZ];

    const int tid = threadIdx.x, warp = tid >> 5;
    const int wm = warp >> 1, wn = warp & 1;
    const int m0 = blockIdx.y * BM, n0 = blockIdx.x * BN;
    const uint32_t sa0 = smem_u32(&sa[0][0]);
    const uint32_t sb0 = smem_u32(&sb[0][0]);

    wmma::fragment<wmma::accumulator, 16, 16, 16, float> c[4][4];
#pragma unroll
    for (int mt = 0; mt < 4; ++mt)
#pragma unroll
        for (int nt = 0; nt < 4; ++nt) wmma::fill_fragment(c[mt][nt], 0.0f);

    stage_pre(sa0, sb0, m0, n0, 0, tid);

    for (int kt = 0; kt < NCHUNK; ++kt) {
        if (kt + 1 < NCHUNK) {
            stage_pre(sa0 + ((kt + 1) & 1) * (TSZ * 2),
                      sb0 + ((kt + 1) & 1) * (TSZ * 2),
                      m0, n0, (kt + 1) * BK, tid);
            asm volatile("cp.async.wait_group 1;" ::: "memory");
        } else {
            asm volatile("cp.async.wait_group 0;" ::: "memory");
        }
        __syncthreads();

        const __nv_bfloat16* pa = &sa[kt & 1][0] + (wm * 64) * LDW;
        const __nv_bfloat16* pb = &sb[kt & 1][0] + (wn * 64) * LDW;
#pragma unroll
        for (int kk = 0; kk < 2; ++kk) {
            wmma::fragment<wmma::matrix_a, 16, 16, 16, __nv_bfloat16,
                           wmma::row_major> af[4];
            wmma::fragment<wmma::matrix_b, 16, 16, 16, __nv_bfloat16,
                           wmma::col_major> bf[4];
#pragma unroll
            for (int mt = 0; mt < 4; ++mt)
                wmma::load_matrix_sync(af[mt], pa + mt * 16 * LDW + kk * 16, LDW);
#pragma unroll
            for (int nt = 0; nt < 4; ++nt)
                wmma::load_matrix_sync(bf[nt], pb + nt * 16 * LDW + kk * 16, LDW);
#pragma unroll
            for (int mt = 0; mt < 4; ++mt)
#pragma unroll
                for (int nt = 0; nt < 4; ++nt)
                    wmma::mma_sync(c[mt][nt], af[mt], bf[nt], c[mt][nt]);
        }
        __syncthreads();
    }

    const size_t crow = (size_t)m0 + wm * 64;
    const int ccol = n0 + wn * 64;
#pragma unroll
    for (int mt = 0; mt < 4; ++mt)
#pragma unroll
        for (int nt = 0; nt < 4; ++nt)
            wmma::store_matrix_sync(g_FW + (crow + mt * 16) * NCOLS + ccol + nt * 16,
                                    c[mt][nt], NCOLS, wmma::mem_row_major);
}

// ---------------------------------------------------------------------------
// Persistent scan v3: cooperative A staging (BK=64, 12 chunks), warp grid
// 2m x 2n x 2k (64x32 warp tiles, intra-CTA k-split -> 8 partial slabs),
// h in registers. CTA c: ni=c&31, ki=c>>5; batch b==c combine owner.
// ---------------------------------------------------------------------------
extern __shared__ __align__(16) unsigned char dynsmem[];

__global__ __launch_bounds__(SCAN_THREADS) void scan_kernel(
    const float* __restrict__ gates, const float* __restrict__ Urb,
    const float* __restrict__ Ub, const int* __restrict__ nf,
    const float* __restrict__ mem_old, float* __restrict__ out) {
    __nv_bfloat16* sB = (__nv_bfloat16*)dynsmem;               // [64][LDBP]
    __nv_bfloat16* sA = (__nv_bfloat16*)(dynsmem + SB_BYTES);  // [2][128][LDA2]

    const int tid = threadIdx.x;
    const int cta = blockIdx.x;
    const int ni = cta & 31, ki = cta >> 5;
    const int n0 = ni * NSLICE;
    const int k0 = ki * KSLICE;
    const int warp = tid >> 5;
    const int wm = warp & 1, wn = (warp >> 1) & 1, wk = warp >> 2;

    // ---- load resident B slice [64 rows][768 k]: 96 x 16B per row ----
    for (int v = tid; v < NSLICE * 96; v += SCAN_THREADS) {
        int row = v / 96, kv = v % 96;
        *(uint4*)(sB + (size_t)row * LDBP + kv * 8) =
            *(const uint4*)(g_Bu + (size_t)(n0 + row) * KP + k0 + kv * 8);
    }

    // ---- h lives in registers: thread owns dims [4*tid, 4*tid+4) ----
    const int d = tid * 4;
    float4 h4 = *(const float4*)(mem_old + (size_t)cta * DIM + d);
    const float4 br4 = *(const float4*)(Urb + d);
    const float4 bu4 = *(const float4*)(Ub + d);
    const int tout = nf[cta] - 1;
    {
        __nv_bfloat16* row = g_Ah + (size_t)cta * KP;
        float hv[4] = {h4.x, h4.y, h4.z, h4.w};
        __nv_bfloat16 hi[4], lo[4];
#pragma unroll
        for (int j = 0; j < 4; ++j) {
            hi[j] = __float2bfloat16(hv[j]);
            lo[j] = __float2bfloat16(hv[j] - __bfloat162float(hi[j]));
        }
        uint32_t hi01 = ((uint32_t*)hi)[0], hi23 = ((uint32_t*)hi)[1];
        uint32_t lo01 = ((uint32_t*)lo)[0], lo23 = ((uint32_t*)lo)[1];
        *(uint2*)(row + d)        = make_uint2(hi01, hi23);
        *(uint2*)(row + 1024 + d) = make_uint2(hi01, hi23);
        *(uint2*)(row + 2048 + d) = make_uint2(lo01, lo23);
    }
    grid_barrier();   // g_Ah + sB ready everywhere

    const uint32_t sa0 = smem_u32(sA);
    const __nv_bfloat16* Abase = g_Ah + k0;

    for (int t = 0; t < TSTEPS; ++t) {
        wmma::fragment<wmma::accumulator, 16, 16, 16, float> c[4][2];
#pragma unroll
        for (int mt = 0; mt < 4; ++mt)
#pragma unroll
            for (int nt = 0; nt < 2; ++nt) wmma::fill_fragment(c[mt][nt], 0.0f);

        // cooperative stage of chunk 0: 128 rows x 64k = 1024 x 16B vectors
        {
#pragma unroll
            for (int j = 0; j < 4; ++j) {
                int v = tid + SCAN_THREADS * j;
                int row = v >> 3, kv = v & 7;
                cpasync16(sa0 + row * (LDA2 * 2) + kv * 16,
                          Abase + (size_t)row * KP + kv * 8);
            }
            asm volatile("cp.async.commit_group;" ::: "memory");
        }

        for (int kt = 0; kt < NCH_S; ++kt) {            // 12 chunks of 64k
            if (kt + 1 < NCH_S) {
                uint32_t dst = sa0 + ((kt + 1) & 1) * (AT_ELEMS * 2);
                const __nv_bfloat16* src = Abase + (kt + 1) * 64;
#pragma unroll
                for (int j = 0; j < 4; ++j) {
                    int v = tid + SCAN_THREADS * j;
                    int row = v >> 3, kv = v & 7;
                    cpasync16(dst + row * (LDA2 * 2) + kv * 16,
                              src + (size_t)row * KP + kv * 8);
                }
                asm volatile("cp.async.commit_group;" ::: "memory");
                asm volatile("cp.async.wait_group 1;" ::: "memory");
            } else {
                asm volatile("cp.async.wait_group 0;" ::: "memory");
            }
            __syncthreads();

            const __nv_bfloat16* pa = sA + (kt & 1) * AT_ELEMS +
                                      (size_t)(wm * 64) * LDA2;
            const __nv_bfloat16* pb = sB + (size_t)(wn * 32) * LDBP + kt * 64;
#pragma unroll
            for (int kk = 0; kk < 2; ++kk) {            // this group's 2 k16s
                const int kc = (wk * 2 + kk) * 16;
                wmma::fragment<wmma::matrix_a, 16, 16, 16, __nv_bfloat16,
                               wmma::row_major> af[4];
                wmma::fragment<wmma::matrix_b, 16, 16, 16, __nv_bfloat16,
                               wmma::col_major> bf[2];
#pragma unroll
                for (int mt = 0; mt < 4; ++mt)
                    wmma::load_matrix_sync(af[mt], pa + mt * 16 * LDA2 + kc, LDA2);
#pragma unroll
                for (int nt = 0; nt < 2; ++nt)
                    wmma::load_matrix_sync(bf[nt],
                                           pb + (size_t)nt * 16 * LDBP + kc, LDBP);
#pragma unroll
                for (int mt = 0; mt < 4; ++mt)
#pragma unroll
                    for (int nt = 0; nt < 2; ++nt)
                        wmma::mma_sync(c[mt][nt], af[mt], bf[nt], c[mt][nt]);
            }
            __syncthreads();                            // protect WAR on buf
        }

        // write partials: slab = ki*2 + wk
        {
            float* base = g_part + (size_t)(ki * 2 + wk) * BATCH * NCOLS;
#pragma unroll
            for (int mt = 0; mt < 4; ++mt)
#pragma unroll
                for (int nt = 0; nt < 2; ++nt)
                    wmma::store_matrix_sync(
                        base + (size_t)(wm * 64 + mt * 16) * NCOLS + n0 + wn * 32 + nt * 16,
                        c[mt][nt], NCOLS, wmma::mem_row_major);
        }
        grid_barrier();   // partials published + visible everywhere

        // ===== combine: this CTA handles batch b == cta; 4 dims/thread =====
        {
            const float gt = gates[cta * TSTEPS + t];
            const float* fw = g_FW + ((size_t)cta * TSTEPS + t) * NCOLS;
            float4 pr = make_float4(0.f, 0.f, 0.f, 0.f);
            float4 pu = make_float4(0.f, 0.f, 0.f, 0.f);
#pragma unroll
            for (int s = 0; s < KSL; ++s) {
                const float* pb0 = g_part + (size_t)s * BATCH * NCOLS +
                                   (size_t)cta * NCOLS + d;
                float4 a = __ldcg((const float4*)pb0);
                float4 b = __ldcg((const float4*)(pb0 + 1024));
                pr.x += a.x; pr.y += a.y; pr.z += a.z; pr.w += a.w;
                pu.x += b.x; pu.y += b.y; pu.z += b.z; pu.w += b.w;
            }
            float4 fr = *(const float4*)(fw + d);
            float4 fu = *(const float4*)(fw + 1024 + d);

            float prv[4] = {pr.x, pr.y, pr.z, pr.w};
            float puv[4] = {pu.x, pu.y, pu.z, pu.w};
            float frv[4] = {fr.x, fr.y, fr.z, fr.w};
            float fuv[4] = {fu.x, fu.y, fu.z, fu.w};
            float brv[4] = {br4.x, br4.y, br4.z, br4.w};
            float buv[4] = {bu4.x, bu4.y, bu4.z, bu4.w};
            float hov[4] = {h4.x, h4.y, h4.z, h4.w};
            float hn[4];
            __nv_bfloat16 hi[4], lo[4];
#pragma unroll
            for (int j = 0; j < 4; ++j) {
                float r = 1.f / (1.f + expf(-(frv[j] + prv[j] + brv[j])));
                float ht = tanhf(fuv[j] + r * (puv[j] + buv[j]));
                hn[j] = gt * ht + (1.f - gt) * hov[j];
                hi[j] = __float2bfloat16(hn[j]);
                lo[j] = __float2bfloat16(hn[j] - __bfloat162float(hi[j]));
            }
            h4 = make_float4(hn[0], hn[1], hn[2], hn[3]);

            __nv_bfloat16* row = g_Ah + (size_t)cta * KP;
            uint32_t hi01 = ((uint32_t*)hi)[0], hi23 = ((uint32_t*)hi)[1];
            uint32_t lo01 = ((uint32_t*)lo)[0], lo23 = ((uint32_t*)lo)[1];
            *(uint2*)(row + d)        = make_uint2(hi01, hi23);
            *(uint2*)(row + 1024 + d) = make_uint2(hi01, hi23);
            *(uint2*)(row + 2048 + d) = make_uint2(lo01, lo23);

            if (t == tout) *(float4*)(out + (size_t)cta * DIM + d) = h4;
        }
        grid_barrier();   // repacked h published before next step's GEMM
    }
}

// ---------------------------------------------------------------------------
// packing kernels
// ---------------------------------------------------------------------------
__global__ void pack_w_kernel(const float* __restrict__ w0,
                              const float* __restrict__ w1, int which) {
    __nv_bfloat16* dst = (which == 0) ? g_Bf : g_Bu;
    size_t i = (size_t)blockIdx.x * blockDim.x + threadIdx.x;
    int n = (int)(i >> 10), k = (int)(i & 1023);
    float v = (n < 1024) ? w0[(size_t)n * 1024 + k] : w1[(size_t)(n - 1024) * 1024 + k];
    __nv_bfloat16 hi = __float2bfloat16(v);
    __nv_bfloat16 lo = __float2bfloat16(v - __bfloat162float(hi));
    __nv_bfloat16* row = dst + (size_t)n * KP;
    row[k] = hi; row[1024 + k] = lo; row[2048 + k] = hi;
}

__global__ void pack_facts_kernel(const float* __restrict__ facts) {
    size_t i = (size_t)blockIdx.x * blockDim.x + threadIdx.x;
    size_t r = i >> 10; int k = (int)(i & 1023);
    float v = facts[i];
    __nv_bfloat16 hi = __float2bfloat16(v);
    __nv_bfloat16 lo = __float2bfloat16(v - __bfloat162float(hi));
    __nv_bfloat16* row = g_Af + r * KP;
    row[k] = hi; row[1024 + k] = hi; row[2048 + k] = lo;
}

// ---------------------------------------------------------------------------
extern "C" void kernel_launch(void* const* d_in, const int* in_sizes, int n_in,
                              void* d_out, int out_size) {
    const float* facts   = (const float*)d_in[0];
    const int*   nf      = (const int*)d_in[1];
    const float* g       = (const float*)d_in[2];
    const float* mem_old = (const float*)d_in[3];
    const float* Wr      = (const float*)d_in[4];
    const float* Urw     = (const float*)d_in[5];
    const float* Urb     = (const float*)d_in[6];
    const float* W       = (const float*)d_in[7];
    const float* Uw      = (const float*)d_in[8];
    const float* Ub      = (const float*)d_in[9];
    float* out = (float*)d_out;

    cudaFuncSetAttribute(scan_kernel,
                         cudaFuncAttributeMaxDynamicSharedMemorySize,
                         SCAN_SMEM);

    pack_w_kernel<<<(2048 * 1024) / 256, 256>>>(Wr, W, /*which=*/0);
    pack_w_kernel<<<(2048 * 1024) / 256, 256>>>(Urw, Uw, /*which=*/1);
    pack_facts_kernel<<<(16384 * 1024) / 256, 256>>>(facts);

    // precompute fWr||fW : [16384, 2048] = A'(facts) @ B'(Wr;W)^T
    gemm_pre<<<dim3(NCOLS / BN, 16384 / BM, 1), 128>>>();

    // all 128 recurrence steps in one persistent launch
    scan_kernel<<<SCAN_CTAS, SCAN_THREADS, SCAN_SMEM>>>(g, Urb, Ub, nf,
                                                        mem_old, out);
}